// round 5
// baseline (speedup 1.0000x reference)
#include <cuda_runtime.h>
#include <cuda_bf16.h>
#include <math.h>
#include <stdint.h>

#define NNODES 20000
#define NGROUP 400
#define MAXG   512

// ---------------- scratch (static device allocations; no cudaMalloc) ----------
__device__ float g_bufA[NNODES * 256];
__device__ float g_bufB[NNODES * 256];
__device__ __nv_bfloat16 g_actH[NNODES * 256];
__device__ __nv_bfloat16 g_actL[NNODES * 256];
__device__ int   g_members[NGROUP * MAXG];
__device__ int   g_cnt[NGROUP];
__device__ float g_dis[NNODES];
__device__ int   g_is64;

// bf16 hi/lo transposed weights: [N][K] row-major
__device__ __nv_bfloat16 g_w1h[256 * 128], g_w1l[256 * 128];
__device__ __nv_bfloat16 g_w2h[256 * 256], g_w2l[256 * 256];
__device__ __nv_bfloat16 g_w3h[128 * 256], g_w3l[128 * 256];

__device__ __forceinline__ uint32_t pack_bf16x2(float a, float b) {
    __nv_bfloat162 t = __floats2bfloat162_rn(a, b);
    return *reinterpret_cast<uint32_t*>(&t);
}

// ---------------- 0) dtype detection for idx ---------------------------------
__global__ void detect_dtype(const int* __restrict__ idx32, int n) {
    int i = threadIdx.x;
    bool bad = false;
    if (i < n / 2) {
        int lo = idx32[2 * i];
        int hi = idx32[2 * i + 1];
        bad = (hi != 0) || (lo < 0) || (lo >= NGROUP);
    }
    unsigned m = __ballot_sync(0xffffffffu, bad);
    __shared__ unsigned s_any[8];
    if ((threadIdx.x & 31) == 0) s_any[threadIdx.x >> 5] = m;
    __syncthreads();
    if (threadIdx.x == 0) {
        unsigned any = 0;
#pragma unroll
        for (int w = 0; w < 8; w++) any |= s_any[w];
        g_is64 = (any == 0) ? 1 : 0;
    }
}

// ---------------- 1) group build (4 elems/thread/tile) ------------------------
__global__ __launch_bounds__(256) void build_groups(const void* __restrict__ idx_raw, int n) {
    const int g    = blockIdx.x;
    const int tid  = threadIdx.x;
    const int lane = tid & 31;
    const int warp = tid >> 5;
    const int is64 = g_is64;
    const int*       idx32 = (const int*)idx_raw;
    const long long* idx64 = (const long long*)idx_raw;

    __shared__ int warp_sums[8];
    __shared__ int s_base;
    if (tid == 0) s_base = 0;
    __syncthreads();

    for (int t0 = 0; t0 < n; t0 += 1024) {
        int i0 = t0 + tid * 4;
        int v[4];
        if (!is64 && i0 + 3 < n) {
            int4 q = *reinterpret_cast<const int4*>(&idx32[i0]);
            v[0] = q.x; v[1] = q.y; v[2] = q.z; v[3] = q.w;
        } else {
#pragma unroll
            for (int j = 0; j < 4; j++) {
                int i = i0 + j;
                v[j] = (i < n) ? (is64 ? (int)idx64[i] : idx32[i]) : -1;
            }
        }
        unsigned m[4];
#pragma unroll
        for (int j = 0; j < 4; j++) m[j] = __ballot_sync(0xffffffffu, v[j] == g);
        unsigned lt = (1u << lane) - 1u;
        int lanebase = 0, wtotal = 0;
#pragma unroll
        for (int j = 0; j < 4; j++) { lanebase += __popc(m[j] & lt); wtotal += __popc(m[j]); }
        if (lane == 0) warp_sums[warp] = wtotal;
        __syncthreads();
        int woff = 0, tile_total = 0;
#pragma unroll
        for (int w = 0; w < 8; w++) {
            if (w < warp) woff += warp_sums[w];
            tile_total += warp_sums[w];
        }
        int mycnt = 0;
#pragma unroll
        for (int j = 0; j < 4; j++) {
            if (v[j] == g) {
                int pos = s_base + woff + lanebase + mycnt;
                g_members[g * MAXG + pos] = i0 + j;
                g_dis[i0 + j] = rsqrtf((float)(pos + 1));
                mycnt++;
            }
        }
        __syncthreads();
        if (tid == 0) s_base += tile_total;
        __syncthreads();
    }
    if (tid == 0) g_cnt[g] = s_base;
}

// ---------------- 2a) weight prep: tiled transpose + bf16 hi/lo split ---------
// grid (K/32, N/32), block (32,8); W fp32 [K][N] -> oh/ol bf16 [N][K]
__global__ __launch_bounds__(256) void prep_w_t(const float* __restrict__ W,
                                                __nv_bfloat16* __restrict__ oh,
                                                __nv_bfloat16* __restrict__ ol, int K, int N) {
    __shared__ __nv_bfloat16 shh[32][33], shl[32][33];
    const int k0 = blockIdx.x * 32, n0 = blockIdx.y * 32;
    const int tx = threadIdx.x, ty = threadIdx.y;
#pragma unroll
    for (int j = 0; j < 4; j++) {
        int kk = ty + j * 8;
        float v = W[(size_t)(k0 + kk) * N + n0 + tx];
        __nv_bfloat16 h = __float2bfloat16(v);
        shh[kk][tx] = h;
        shl[kk][tx] = __float2bfloat16(v - __bfloat162float(h));
    }
    __syncthreads();
#pragma unroll
    for (int j = 0; j < 4; j++) {
        int nn = ty + j * 8;
        oh[(size_t)(n0 + nn) * K + k0 + tx] = shh[tx][nn];
        ol[(size_t)(n0 + nn) * K + k0 + tx] = shl[tx][nn];
    }
}

// ---------------- 2b) activation fp32 -> bf16 hi/lo (for layer-1 input) -------
__global__ void conv_split(const float* __restrict__ A, __nv_bfloat16* __restrict__ oh,
                           __nv_bfloat16* __restrict__ ol, int total4) {
    int e = blockIdx.x * 256 + threadIdx.x;
    if (e >= total4) return;
    float4 a = *reinterpret_cast<const float4*>(&A[(size_t)e * 4]);
    __nv_bfloat16 h0 = __float2bfloat16(a.x), h1 = __float2bfloat16(a.y);
    __nv_bfloat16 h2 = __float2bfloat16(a.z), h3 = __float2bfloat16(a.w);
    uint2 uh, ul;
    uh.x = ((uint32_t)*(uint16_t*)&h1 << 16) | *(uint16_t*)&h0;
    uh.y = ((uint32_t)*(uint16_t*)&h3 << 16) | *(uint16_t*)&h2;
    ul.x = pack_bf16x2(a.x - __bfloat162float(h0), a.y - __bfloat162float(h1));
    ul.y = pack_bf16x2(a.z - __bfloat162float(h2), a.w - __bfloat162float(h3));
    *reinterpret_cast<uint2*>(&oh[(size_t)e * 4]) = uh;
    *reinterpret_cast<uint2*>(&ol[(size_t)e * 4]) = ul;
}

// ---------------- 3) HMMA GEMM: C[M,BN] = A @ W^T ----------------------------
// A bf16 hi/lo [M][K]; W bf16 hi/lo [BN][K]; BM=64, full-N CTA, BK=32.
// 8 warps: 2(M) x 4(N); warp tile 32 x (BN/4); 3-split bf16 MMA, fp32 accum.
#define LDMX4(r0, r1, r2, r3, addr) \
    asm volatile("ldmatrix.sync.aligned.m8n8.x4.shared.b16 {%0,%1,%2,%3}, [%4];" \
                 : "=r"(r0), "=r"(r1), "=r"(r2), "=r"(r3) : "r"(addr))
#define MMA16816(c, a, b) \
    asm volatile("mma.sync.aligned.m16n8k16.row.col.f32.bf16.bf16.f32 " \
                 "{%0,%1,%2,%3}, {%4,%5,%6,%7}, {%8,%9}, {%0,%1,%2,%3};" \
                 : "+f"((c)[0]), "+f"((c)[1]), "+f"((c)[2]), "+f"((c)[3]) \
                 : "r"((a)[0]), "r"((a)[1]), "r"((a)[2]), "r"((a)[3]), \
                   "r"((b)[0]), "r"((b)[1]))

template <int BN>
__global__ __launch_bounds__(256, 2) void gemm_mma(const __nv_bfloat16* __restrict__ Ah,
                                                   const __nv_bfloat16* __restrict__ Al,
                                                   const __nv_bfloat16* __restrict__ Wh,
                                                   const __nv_bfloat16* __restrict__ Wl,
                                                   float* __restrict__ C, int M, int K) {
    extern __shared__ __nv_bfloat16 smem[];
    __nv_bfloat16* sAh = smem;                    // 64*40
    __nv_bfloat16* sAl = smem + 64 * 40;
    __nv_bfloat16* sBh = smem + 64 * 40 * 2;      // BN*40
    __nv_bfloat16* sBl = sBh + BN * 40;

    const int tid  = threadIdx.x;
    const int wid  = tid >> 5;
    const int lane = tid & 31;
    const int bm   = blockIdx.x * 64;
    const int wm   = (wid & 1) * 32;
    const int wn   = (wid >> 1) * (BN / 4);
    constexpr int NT = BN / 32;          // n-tiles (n8) per warp
    constexpr int NG = NT / 2;           // ldmatrix groups of 16

    float acc[2][NT][4];
#pragma unroll
    for (int i = 0; i < 2; i++)
#pragma unroll
        for (int j = 0; j < NT; j++)
#pragma unroll
            for (int q = 0; q < 4; q++) acc[i][j][q] = 0.0f;

    const int lrow = lane & 15;
    const int lcol = (lane >> 4) << 3;
    const uint2 z2 = make_uint2(0u, 0u);

    for (int kc = 0; kc < K; kc += 32) {
        __syncthreads();
        // A fill: 64 rows x 32 k (hi + lo), uint2 (4 bf16) per store
#pragma unroll
        for (int e = tid; e < 64 * 8; e += 256) {
            int row = e >> 3, seg = (e & 7) << 2;
            size_t gi = (size_t)(bm + row) * K + kc + seg;
            bool ok = (bm + row) < M;
            *reinterpret_cast<uint2*>(&sAh[row * 40 + seg]) =
                ok ? *reinterpret_cast<const uint2*>(&Ah[gi]) : z2;
            *reinterpret_cast<uint2*>(&sAl[row * 40 + seg]) =
                ok ? *reinterpret_cast<const uint2*>(&Al[gi]) : z2;
        }
        // B fill: BN rows x 32 k (hi + lo)
#pragma unroll
        for (int e = tid; e < BN * 8; e += 256) {
            int row = e >> 3, seg = (e & 7) << 2;
            size_t gi = (size_t)row * K + kc + seg;
            *reinterpret_cast<uint2*>(&sBh[row * 40 + seg]) = *reinterpret_cast<const uint2*>(&Wh[gi]);
            *reinterpret_cast<uint2*>(&sBl[row * 40 + seg]) = *reinterpret_cast<const uint2*>(&Wl[gi]);
        }
        __syncthreads();

#pragma unroll
        for (int ks = 0; ks < 2; ks++) {
            const int k0 = ks * 16;
            uint32_t ah[2][4], al[2][4];
#pragma unroll
            for (int mi = 0; mi < 2; mi++) {
                uint32_t adrh = (uint32_t)__cvta_generic_to_shared(&sAh[(wm + mi * 16 + lrow) * 40 + k0 + lcol]);
                uint32_t adrl = (uint32_t)__cvta_generic_to_shared(&sAl[(wm + mi * 16 + lrow) * 40 + k0 + lcol]);
                LDMX4(ah[mi][0], ah[mi][1], ah[mi][2], ah[mi][3], adrh);
                LDMX4(al[mi][0], al[mi][1], al[mi][2], al[mi][3], adrl);
            }
#pragma unroll
            for (int nj = 0; nj < NG; nj++) {
                uint32_t r0, r1, r2, r3;
                uint32_t bh0[2], bh1[2], bl0[2], bl1[2];
                uint32_t adrh = (uint32_t)__cvta_generic_to_shared(&sBh[(wn + nj * 16 + lrow) * 40 + k0 + lcol]);
                LDMX4(r0, r1, r2, r3, adrh);
                bh0[0] = r0; bh0[1] = r2; bh1[0] = r1; bh1[1] = r3;
                uint32_t adrl = (uint32_t)__cvta_generic_to_shared(&sBl[(wn + nj * 16 + lrow) * 40 + k0 + lcol]);
                LDMX4(r0, r1, r2, r3, adrl);
                bl0[0] = r0; bl0[1] = r2; bl1[0] = r1; bl1[1] = r3;
#pragma unroll
                for (int mi = 0; mi < 2; mi++) {
                    MMA16816(acc[mi][nj * 2 + 0], ah[mi], bh0);
                    MMA16816(acc[mi][nj * 2 + 0], al[mi], bh0);
                    MMA16816(acc[mi][nj * 2 + 0], ah[mi], bl0);
                    MMA16816(acc[mi][nj * 2 + 1], ah[mi], bh1);
                    MMA16816(acc[mi][nj * 2 + 1], al[mi], bh1);
                    MMA16816(acc[mi][nj * 2 + 1], ah[mi], bl1);
                }
            }
        }
    }

    // ---- epilogue ----
    const int trow = lane >> 2;
    const int tcol = (lane & 3) * 2;
#pragma unroll
    for (int mi = 0; mi < 2; mi++) {
        int r0 = bm + wm + mi * 16 + trow;
#pragma unroll
        for (int nt = 0; nt < NT; nt++) {
            int c0 = wn + nt * 8 + tcol;
            if (r0 < M)
                *reinterpret_cast<float2*>(&C[(size_t)r0 * BN + c0]) =
                    make_float2(acc[mi][nt][0], acc[mi][nt][1]);
            if (r0 + 8 < M)
                *reinterpret_cast<float2*>(&C[(size_t)(r0 + 8) * BN + c0]) =
                    make_float2(acc[mi][nt][2], acc[mi][nt][3]);
        }
    }
}

// ---------------- 4) per-group prefix scan + bias + relu (batch-4 prefetch) ---
// BF16OUT=1: write bf16 hi/lo (next layer's A). Else fp32.
template <int BF16OUT>
__global__ __launch_bounds__(128) void scan_relu(const float* __restrict__ H,
                                                 const float* __restrict__ bias,
                                                 float* __restrict__ outF,
                                                 __nv_bfloat16* __restrict__ outH,
                                                 __nv_bfloat16* __restrict__ outL, int D) {
    __shared__ int   s_mem[MAXG];
    __shared__ float s_dis[MAXG];
    const int g = blockIdx.x;
    const int c = g_cnt[g];
    for (int m = threadIdx.x; m < c; m += 128) {
        int i = g_members[g * MAXG + m];
        s_mem[m] = i;
        s_dis[m] = g_dis[i];
    }
    __syncthreads();
    const int f = blockIdx.y * 128 + threadIdx.x;
    float acc = 0.0f;
    const float bf = bias[f];
    for (int m = 0; m < c; m += 4) {
        float v[4], dd[4];
        int   id[4];
#pragma unroll
        for (int j = 0; j < 4; j++) {
            if (m + j < c) {
                id[j] = s_mem[m + j];
                dd[j] = s_dis[m + j];
                v[j]  = H[(size_t)id[j] * D + f];
            }
        }
#pragma unroll
        for (int j = 0; j < 4; j++) {
            if (m + j < c) {
                acc = fmaf(dd[j], v[j], acc);
                float o = fmaxf(fmaf(dd[j], acc, bf), 0.0f);
                size_t oi = (size_t)id[j] * D + f;
                if (BF16OUT) {
                    __nv_bfloat16 h = __float2bfloat16(o);
                    outH[oi] = h;
                    outL[oi] = __float2bfloat16(o - __bfloat162float(h));
                } else {
                    outF[oi] = o;
                }
            }
        }
    }
}

// ---------------- 5) LayerNorm over last dim (128) ----------------------------
__global__ __launch_bounds__(256) void layernorm128(const float* __restrict__ h,
                                                    const float* __restrict__ gamma,
                                                    const float* __restrict__ beta,
                                                    float* __restrict__ out, int n) {
    int row = blockIdx.x * (blockDim.x >> 5) + (threadIdx.x >> 5);
    if (row >= n) return;
    int lane = threadIdx.x & 31;
    float4 v = reinterpret_cast<const float4*>(h + (size_t)row * 128)[lane];
    float s = v.x + v.y + v.z + v.w;
#pragma unroll
    for (int o = 16; o; o >>= 1) s += __shfl_xor_sync(0xffffffffu, s, o);
    float mu = s * (1.0f / 128.0f);
    float dx = v.x - mu, dy = v.y - mu, dz = v.z - mu, dw = v.w - mu;
    float q = dx * dx + dy * dy + dz * dz + dw * dw;
#pragma unroll
    for (int o = 16; o; o >>= 1) q += __shfl_xor_sync(0xffffffffu, q, o);
    float inv = rsqrtf(q * (1.0f / 128.0f) + 1e-5f);
    float4 ga = reinterpret_cast<const float4*>(gamma)[lane];
    float4 be = reinterpret_cast<const float4*>(beta)[lane];
    float4 o4;
    o4.x = fmaf(dx * inv, ga.x, be.x);
    o4.y = fmaf(dy * inv, ga.y, be.y);
    o4.z = fmaf(dz * inv, ga.z, be.z);
    o4.w = fmaf(dw * inv, ga.w, be.w);
    reinterpret_cast<float4*>(out + (size_t)row * 128)[lane] = o4;
}

// ---------------- launch ------------------------------------------------------
extern "C" void kernel_launch(void* const* d_in, const int* in_sizes, int n_in,
                              void* d_out, int out_size) {
    const float* x     = (const float*)d_in[0];
    const void*  idx   = d_in[1];
    const float* W1    = (const float*)d_in[2];
    const float* b1    = (const float*)d_in[3];
    const float* W2    = (const float*)d_in[4];
    const float* b2    = (const float*)d_in[5];
    const float* W3    = (const float*)d_in[6];
    const float* b3    = (const float*)d_in[7];
    const float* gamma = (const float*)d_in[8];
    const float* beta  = (const float*)d_in[9];
    float* out = (float*)d_out;

    float *bufA, *bufB;
    __nv_bfloat16 *actH, *actL, *w1h, *w1l, *w2h, *w2l, *w3h, *w3l;
    cudaGetSymbolAddress((void**)&bufA, g_bufA);
    cudaGetSymbolAddress((void**)&bufB, g_bufB);
    cudaGetSymbolAddress((void**)&actH, g_actH);
    cudaGetSymbolAddress((void**)&actL, g_actL);
    cudaGetSymbolAddress((void**)&w1h, g_w1h);
    cudaGetSymbolAddress((void**)&w1l, g_w1l);
    cudaGetSymbolAddress((void**)&w2h, g_w2h);
    cudaGetSymbolAddress((void**)&w2l, g_w2l);
    cudaGetSymbolAddress((void**)&w3h, g_w3h);
    cudaGetSymbolAddress((void**)&w3l, g_w3l);

    const int SMEM256 = (64 * 40 * 2 + 256 * 40 * 2) * 2;  // 51200 B
    const int SMEM128 = (64 * 40 * 2 + 128 * 40 * 2) * 2;  // 30720 B
    cudaFuncSetAttribute(gemm_mma<256>, cudaFuncAttributeMaxDynamicSharedMemorySize, SMEM256);
    cudaFuncSetAttribute(gemm_mma<128>, cudaFuncAttributeMaxDynamicSharedMemorySize, SMEM128);

    const int n = NNODES;
    const int mtiles = (n + 63) / 64;  // 313

    detect_dtype<<<1, 256>>>((const int*)idx, n);
    build_groups<<<NGROUP, 256>>>(idx, n);
    prep_w_t<<<dim3(128 / 32, 256 / 32), dim3(32, 8)>>>(W1, w1h, w1l, 128, 256);
    prep_w_t<<<dim3(256 / 32, 256 / 32), dim3(32, 8)>>>(W2, w2h, w2l, 256, 256);
    prep_w_t<<<dim3(256 / 32, 128 / 32), dim3(32, 8)>>>(W3, w3h, w3l, 256, 128);
    conv_split<<<(n * 128 / 4 + 255) / 256, 256>>>(x, actH, actL, n * 128 / 4);

    // layer 1: [20000,128] @ W1 -> bufA[20000,256]
    gemm_mma<256><<<mtiles, 256, SMEM256>>>(actH, actL, w1h, w1l, bufA, n, 128);
    scan_relu<1><<<dim3(NGROUP, 2), 128>>>(bufA, b1, nullptr, actH, actL, 256);
    // layer 2: [20000,256] @ W2 -> bufA
    gemm_mma<256><<<mtiles, 256, SMEM256>>>(actH, actL, w2h, w2l, bufA, n, 256);
    scan_relu<1><<<dim3(NGROUP, 2), 128>>>(bufA, b2, nullptr, actH, actL, 256);
    // layer 3: [20000,256] @ W3 -> bufA (N=128)
    gemm_mma<128><<<mtiles, 256, SMEM128>>>(actH, actL, w3h, w3l, bufA, n, 256);
    scan_relu<0><<<dim3(NGROUP, 1), 128>>>(bufA, b3, bufB, nullptr, nullptr, 128);

    layernorm128<<<(n + 7) / 8, 256>>>(bufB, gamma, beta, out, n);
}